// round 1
// baseline (speedup 1.0000x reference)
#include <cuda_runtime.h>
#include <math.h>

// Problem dims (fixed by the reference)
#define B_ 4
#define I_ 512
#define K_ 512
#define C_ 64
#define EPS_LN 1e-5f

// -------- scratch (device globals; no allocation allowed) --------
__device__ float g_Qa[B_ * K_ * C_];   // Q @ W1^T + b1
__device__ float g_R [B_ * K_ * C_];   // Qa / D
__device__ float g_Va[B_ * I_ * C_];   // softmax-weighted contraction result
__device__ float g_Vp[B_ * I_ * C_];   // V + LN(Va) @ W2^T + b2 (pre-LN2)
__device__ float g_mean1[B_], g_rstd1[B_];
__device__ float g_mean2[B_], g_rstd2[B_];

// ---------------------------------------------------------------
// Kernel 1: Qa[b,k,c] = b1[c] + sum_j Q[b,k,j] * W1[c,j]
// 256 threads = 4 rows x 64 channels. W1 in smem, padded vs bank conflicts.
// ---------------------------------------------------------------
__global__ void k_linear1(const float* __restrict__ Q,
                          const float* __restrict__ W1,
                          const float* __restrict__ b1) {
    __shared__ float Ws[C_][C_ + 1];
    __shared__ float Qs[4][C_];
    int t = threadIdx.x;
    for (int idx = t; idx < C_ * C_; idx += 256)
        Ws[idx / C_][idx % C_] = W1[idx];
    int r = t >> 6, c = t & 63;
    int grow = blockIdx.x * 4 + r;          // row in [0, B_*K_)
    Qs[r][c] = Q[(size_t)grow * C_ + c];
    __syncthreads();
    float acc = b1[c];
#pragma unroll
    for (int j = 0; j < C_; j++)
        acc += Qs[r][j] * Ws[c][j];
    g_Qa[(size_t)grow * C_ + c] = acc;
}

// ---------------------------------------------------------------
// Kernel 2 (pass 1 over z): per (b,k) compute
//   D[c] = sum_i exp(z[b,i,k,c]) * (m[b,i,k] + 1e-6)   (masked rows skipped;
//          their contribution is 1e-6*exp ~ 4e-7 relative — below tolerance)
// then R[b,k,c] = Qa[b,k,c] / D[c].
// 256 threads = 4 i-lanes x 64 channels; coalesced 128B/warp z reads.
// ---------------------------------------------------------------
__global__ void k_pass1(const float* __restrict__ z,
                        const float* __restrict__ zm) {
    int k = blockIdx.x, b = blockIdx.y;
    int t = threadIdx.x;
    int c = t & 63, di = t >> 6;
    const float* zp = z + (((size_t)b * I_) * K_ + k) * C_ + c;
    const float* mp = zm + (size_t)b * I_ * K_ + k;
    float acc = 0.f;
#pragma unroll 4
    for (int i = di; i < I_; i += 4) {
        float m = __ldg(&mp[(size_t)i * K_]);
        if (m != 0.f) {  // warp-uniform: skips the 256B z row entirely
            acc += __expf(zp[(size_t)i * (K_ * C_)]) * (m + 1e-6f);
        }
    }
    __shared__ float red[4][C_];
    red[di][c] = acc;
    __syncthreads();
    if (t < C_) {
        float D = red[0][t] + red[1][t] + red[2][t] + red[3][t];
        size_t off = ((size_t)b * K_ + k) * C_ + t;
        g_R[off] = g_Qa[off] / D;
    }
}

// ---------------------------------------------------------------
// Kernel 3 (pass 2 over z): per (b,i) compute
//   Va[b,i,c] = sum_k m*(m+1e-6) * exp(z[b,i,k,c]) * R[b,k,c]
// Masked (m==0) rows contribute exactly 0 -> skip load.
// R (512KB total) stays L2/L1 resident across i-blocks of the same batch.
// ---------------------------------------------------------------
__global__ void k_pass2(const float* __restrict__ z,
                        const float* __restrict__ zm) {
    int i = blockIdx.x, b = blockIdx.y;
    int t = threadIdx.x;
    int c = t & 63, dk = t >> 6;
    const float* zp = z + (((size_t)b * I_ + i) * K_) * C_ + c;
    const float* mp = zm + ((size_t)b * I_ + i) * K_;
    const float* Rp = g_R + ((size_t)b * K_) * C_ + c;
    float acc = 0.f;
#pragma unroll 4
    for (int k = dk; k < K_; k += 4) {
        float m = __ldg(&mp[k]);
        if (m != 0.f) {  // warp-uniform skip
            float w = m * (m + 1e-6f);
            acc += w * __expf(zp[(size_t)k * C_]) * __ldg(&Rp[(size_t)k * C_]);
        }
    }
    __shared__ float red[4][C_];
    red[dk][c] = acc;
    __syncthreads();
    if (t < C_) {
        g_Va[((size_t)b * I_ + i) * C_ + t] =
            red[0][t] + red[1][t] + red[2][t] + red[3][t];
    }
}

// ---------------------------------------------------------------
// Kernel 4: per-batch mean/rstd over (I_,C_) = 32768 elements.
// which==0: stats of g_Va -> g_mean1/g_rstd1
// which==1: stats of g_Vp -> g_mean2/g_rstd2
// Deterministic (fixed reduction tree), double accumulation.
// ---------------------------------------------------------------
__global__ void k_stats(int which) {
    int b = blockIdx.x;
    const float* p = (which == 0 ? g_Va : g_Vp) + (size_t)b * I_ * C_;
    double s = 0.0, s2 = 0.0;
    for (int idx = threadIdx.x; idx < I_ * C_; idx += blockDim.x) {
        double v = (double)p[idx];
        s += v;
        s2 += v * v;
    }
    __shared__ double sh0[256], sh1[256];
    sh0[threadIdx.x] = s; sh1[threadIdx.x] = s2;
    __syncthreads();
    for (int o = 128; o > 0; o >>= 1) {
        if (threadIdx.x < o) {
            sh0[threadIdx.x] += sh0[threadIdx.x + o];
            sh1[threadIdx.x] += sh1[threadIdx.x + o];
        }
        __syncthreads();
    }
    if (threadIdx.x == 0) {
        const double N = (double)(I_ * C_);
        double mu  = sh0[0] / N;
        double var = sh1[0] / N - mu * mu;
        float rstd = (float)(1.0 / sqrt(var + (double)EPS_LN));
        if (which == 0) { g_mean1[b] = (float)mu; g_rstd1[b] = rstd; }
        else            { g_mean2[b] = (float)mu; g_rstd2[b] = rstd; }
    }
}

// ---------------------------------------------------------------
// Kernel 5: Vp[b,i,c] = V[b,i,c] + b2[c] + sum_j LN1(Va)[b,i,j] * W2[c,j]
// ---------------------------------------------------------------
__global__ void k_linear2(const float* __restrict__ V,
                          const float* __restrict__ W2,
                          const float* __restrict__ b2) {
    __shared__ float Ws[C_][C_ + 1];
    __shared__ float Xs[4][C_];
    int t = threadIdx.x;
    for (int idx = t; idx < C_ * C_; idx += 256)
        Ws[idx / C_][idx % C_] = W2[idx];
    int r = t >> 6, c = t & 63;
    int grow = blockIdx.x * 4 + r;          // row in [0, B_*I_)
    int b = grow >> 9;                      // grow / I_
    float mu = g_mean1[b], rs = g_rstd1[b];
    Xs[r][c] = (g_Va[(size_t)grow * C_ + c] - mu) * rs;
    __syncthreads();
    float acc = b2[c];
#pragma unroll
    for (int j = 0; j < C_; j++)
        acc += Xs[r][j] * Ws[c][j];
    g_Vp[(size_t)grow * C_ + c] = V[(size_t)grow * C_ + c] + acc;
}

// ---------------------------------------------------------------
// Kernel 6: out = (Vp - mean2[b]) * rstd2[b]
// ---------------------------------------------------------------
__global__ void k_final(float* __restrict__ out) {
    int idx = blockIdx.x * blockDim.x + threadIdx.x;
    int b = idx >> 15;                      // idx / (I_*C_)
    out[idx] = (g_Vp[idx] - g_mean2[b]) * g_rstd2[b];
}

// ---------------------------------------------------------------
extern "C" void kernel_launch(void* const* d_in, const int* in_sizes, int n_in,
                              void* d_out, int out_size) {
    const float* V    = (const float*)d_in[0];
    const float* Q    = (const float*)d_in[1];
    const float* z    = (const float*)d_in[2];
    const float* zm   = (const float*)d_in[3];
    const float* W1   = (const float*)d_in[4];
    const float* b1   = (const float*)d_in[5];
    const float* W2   = (const float*)d_in[6];
    const float* b2   = (const float*)d_in[7];
    // d_in[8] = dim (always 1 for this problem)
    float* out = (float*)d_out;

    k_linear1<<<(B_ * K_) / 4, 256>>>(Q, W1, b1);
    k_pass1<<<dim3(K_, B_), 256>>>(z, zm);
    k_pass2<<<dim3(I_, B_), 256>>>(z, zm);
    k_stats<<<B_, 256>>>(0);
    k_linear2<<<(B_ * I_) / 4, 256>>>(V, W2, b2);
    k_stats<<<B_, 256>>>(1);
    k_final<<<(B_ * I_ * C_) / 256, 256>>>(out);
}

// round 2
// speedup vs baseline: 1.7940x; 1.7940x over previous
#include <cuda_runtime.h>
#include <math.h>

#define B_ 4
#define I_ 512
#define K_ 512
#define C_ 64
#define EPS_LN 1e-5f

// -------- scratch (device globals; allocation is forbidden) --------
__device__ float  g_Qa[B_ * K_ * C_];     // Q @ W1^T + b1
__device__ float  g_R [B_ * K_ * C_];     // Qa / D
__device__ float  g_Va[B_ * I_ * C_];     // contraction result (pre-LN1)
__device__ float  g_Vp[B_ * I_ * C_];     // V + LN1(Va)@W2^T + b2 (pre-LN2)
__device__ double2 g_part1[B_ * I_];      // per-(b,i) {sum, sumsq} of Va
__device__ double2 g_part2[(B_ * I_) / 4];// per-linear2-block {sum, sumsq} of Vp
__device__ float  g_mean1[B_], g_rstd1[B_];
__device__ float  g_mean2[B_], g_rstd2[B_];

// ---------------------------------------------------------------
// Kernel 1: Qa[b,k,c] = b1[c] + sum_j Q[b,k,j] * W1[c,j]
// ---------------------------------------------------------------
__global__ void k_linear1(const float* __restrict__ Q,
                          const float* __restrict__ W1,
                          const float* __restrict__ b1) {
    __shared__ float Ws[C_][C_ + 1];
    __shared__ float Qs[4][C_];
    int t = threadIdx.x;
    for (int idx = t; idx < C_ * C_; idx += 256)
        Ws[idx / C_][idx % C_] = W1[idx];
    int r = t >> 6, c = t & 63;
    int grow = blockIdx.x * 4 + r;
    Qs[r][c] = Q[(size_t)grow * C_ + c];
    __syncthreads();
    float acc = b1[c];
#pragma unroll
    for (int j = 0; j < C_; j++)
        acc += Qs[r][j] * Ws[c][j];
    g_Qa[(size_t)grow * C_ + c] = acc;
}

// ---------------------------------------------------------------
// Deterministic active-index compaction (warp ballot + popc prefix,
// fixed order). 512 masks, 8 warps x 2 groups of 32.
// mstride: stride (in floats) between consecutive mask entries.
// weight mode 0: store (m + 1e-6)         [pass1]
// weight mode 1: store m * (m + 1e-6)     [pass2]
// ---------------------------------------------------------------
template<int WMODE>
__device__ __forceinline__ int compact_active(const float* __restrict__ mp,
                                              size_t mstride,
                                              int* s_idx, float* s_w,
                                              int* s_cnt, int* s_off) {
    int t = threadIdx.x;
    int lane = t & 31, wid = t >> 5;
    float mv[2]; unsigned bal[2];
#pragma unroll
    for (int q = 0; q < 2; q++) {
        int g = wid + q * 8;
        int i = g * 32 + lane;
        mv[q] = __ldg(&mp[(size_t)i * mstride]);
        bal[q] = __ballot_sync(0xffffffffu, mv[q] != 0.f);
        if (lane == 0) s_cnt[g] = __popc(bal[q]);
    }
    __syncthreads();
    if (t == 0) {
        int acc = 0;
#pragma unroll
        for (int g = 0; g < 16; g++) { s_off[g] = acc; acc += s_cnt[g]; }
        s_off[16] = acc;
    }
    __syncthreads();
#pragma unroll
    for (int q = 0; q < 2; q++) {
        int g = wid + q * 8;
        int i = g * 32 + lane;
        if (mv[q] != 0.f) {
            int pos = s_off[g] + __popc(bal[q] & ((1u << lane) - 1u));
            s_idx[pos] = i;
            s_w[pos] = (WMODE == 0) ? (mv[q] + 1e-6f)
                                    : (mv[q] * (mv[q] + 1e-6f));
        }
    }
    __syncthreads();
    return s_off[16];
}

// ---------------------------------------------------------------
// Kernel 2 (pass 1 over z): per (b,k):
//   D[c] = sum_{active i} exp(z[b,i,k,c]) * (m+1e-6)
//   R[b,k,c] = Qa[b,k,c] / D[c]
// 256 thr = 16 row-lanes x 16 float4-channel-groups. Branch-free loop.
// ---------------------------------------------------------------
__global__ void k_pass1(const float* __restrict__ z,
                        const float* __restrict__ zm) {
    int k = blockIdx.x, b = blockIdx.y;
    int t = threadIdx.x;
    __shared__ int   s_idx[I_];
    __shared__ float s_w[I_];
    __shared__ int   s_cnt[16];
    __shared__ int   s_off[17];
    __shared__ float4 red[16][16];

    const float* mp = zm + (size_t)b * I_ * K_ + k;
    int nact = compact_active<0>(mp, K_, s_idx, s_w, s_cnt, s_off);

    int c4 = t & 15;        // float4 channel group
    int di = t >> 4;        // row lane
    const float4* zb = (const float4*)z
        + (((size_t)b * I_) * K_ + k) * (C_ / 4) + c4;
    const size_t zstride = (size_t)K_ * (C_ / 4);   // per-i stride in float4

    float4 acc = make_float4(0.f, 0.f, 0.f, 0.f);
#pragma unroll 4
    for (int j = di; j < nact; j += 16) {
        int i = s_idx[j];
        float w = s_w[j];
        float4 zv = __ldg(&zb[(size_t)i * zstride]);
        acc.x += __expf(zv.x) * w;
        acc.y += __expf(zv.y) * w;
        acc.z += __expf(zv.z) * w;
        acc.w += __expf(zv.w) * w;
    }
    red[di][c4] = acc;
    __syncthreads();
    if (t < 16) {
        float4 D = red[0][t];
#pragma unroll
        for (int r = 1; r < 16; r++) {
            float4 v = red[r][t];
            D.x += v.x; D.y += v.y; D.z += v.z; D.w += v.w;
        }
        size_t off = ((size_t)b * K_ + k) * (C_ / 4) + t;
        float4 qa = ((const float4*)g_Qa)[off];
        float4 R = make_float4(qa.x / D.x, qa.y / D.y, qa.z / D.z, qa.w / D.w);
        ((float4*)g_R)[off] = R;
    }
}

// ---------------------------------------------------------------
// Kernel 3 (pass 2 over z): per (b,i):
//   Va[b,i,c] = sum_{active k} m*(m+1e-6) * exp(z[b,i,k,c]) * R[b,k,c]
// Also emits per-row double {sum, sumsq} partials for LN1 stats.
// ---------------------------------------------------------------
__global__ void k_pass2(const float* __restrict__ z,
                        const float* __restrict__ zm) {
    int i = blockIdx.x, b = blockIdx.y;
    int t = threadIdx.x;
    __shared__ int   s_idx[K_];
    __shared__ float s_w[K_];
    __shared__ int   s_cnt[16];
    __shared__ int   s_off[17];
    __shared__ float4 red[16][16];
    __shared__ double sd[16], sd2[16];

    const float* mp = zm + ((size_t)b * I_ + i) * K_;
    int nact = compact_active<1>(mp, 1, s_idx, s_w, s_cnt, s_off);

    int c4 = t & 15;
    int dk = t >> 4;
    const float4* zb = (const float4*)z
        + (((size_t)b * I_ + i) * K_) * (C_ / 4) + c4;
    const float4* Rb = (const float4*)g_R + ((size_t)b * K_) * (C_ / 4) + c4;

    float4 acc = make_float4(0.f, 0.f, 0.f, 0.f);
#pragma unroll 4
    for (int j = dk; j < nact; j += 16) {
        int kk = s_idx[j];
        float w = s_w[j];
        float4 zv = __ldg(&zb[(size_t)kk * (C_ / 4)]);
        float4 Rv = __ldg(&Rb[(size_t)kk * (C_ / 4)]);
        acc.x += w * __expf(zv.x) * Rv.x;
        acc.y += w * __expf(zv.y) * Rv.y;
        acc.z += w * __expf(zv.z) * Rv.z;
        acc.w += w * __expf(zv.w) * Rv.w;
    }
    red[dk][c4] = acc;
    __syncthreads();
    if (t < 16) {
        float4 v = red[0][t];
#pragma unroll
        for (int r = 1; r < 16; r++) {
            float4 u = red[r][t];
            v.x += u.x; v.y += u.y; v.z += u.z; v.w += u.w;
        }
        ((float4*)g_Va)[((size_t)b * I_ + i) * (C_ / 4) + t] = v;
        double s  = (double)v.x + (double)v.y + (double)v.z + (double)v.w;
        double s2 = (double)v.x * v.x + (double)v.y * v.y
                  + (double)v.z * v.z + (double)v.w * v.w;
        sd[t] = s; sd2[t] = s2;
    }
    __syncthreads();
    if (t == 0) {
        double s = 0.0, s2 = 0.0;
#pragma unroll
        for (int r = 0; r < 16; r++) { s += sd[r]; s2 += sd2[r]; }
        g_part1[(size_t)b * I_ + i] = make_double2(s, s2);
    }
}

// ---------------------------------------------------------------
// Tiny stats reduce: combine partials -> per-batch mean/rstd.
// which==0: g_part1 (512/batch) -> mean1/rstd1
// which==1: g_part2 (128/batch) -> mean2/rstd2
// ---------------------------------------------------------------
__global__ void k_reduce(int which) {
    int b = blockIdx.x;
    int n = (which == 0) ? I_ : (I_ / 4);
    const double2* p = (which == 0 ? g_part1 : g_part2) + (size_t)b * n;
    double s = 0.0, s2 = 0.0;
    for (int j = threadIdx.x; j < n; j += 256) {
        double2 v = p[j];
        s += v.x; s2 += v.y;
    }
    __shared__ double sh0[256], sh1[256];
    sh0[threadIdx.x] = s; sh1[threadIdx.x] = s2;
    __syncthreads();
    for (int o = 128; o > 0; o >>= 1) {
        if (threadIdx.x < o) {
            sh0[threadIdx.x] += sh0[threadIdx.x + o];
            sh1[threadIdx.x] += sh1[threadIdx.x + o];
        }
        __syncthreads();
    }
    if (threadIdx.x == 0) {
        const double N = (double)(I_ * C_);
        double mu  = sh0[0] / N;
        double var = sh1[0] / N - mu * mu;
        float rstd = (float)(1.0 / sqrt(var + (double)EPS_LN));
        if (which == 0) { g_mean1[b] = (float)mu; g_rstd1[b] = rstd; }
        else            { g_mean2[b] = (float)mu; g_rstd2[b] = rstd; }
    }
}

// ---------------------------------------------------------------
// Kernel 5: Vp = V + LN1(Va) @ W2^T + b2 ; emits per-block LN2 partials.
// ---------------------------------------------------------------
__global__ void k_linear2(const float* __restrict__ V,
                          const float* __restrict__ W2,
                          const float* __restrict__ b2) {
    __shared__ float Ws[C_][C_ + 1];
    __shared__ float Xs[4][C_];
    __shared__ double sh0[256], sh1[256];
    int t = threadIdx.x;
    for (int idx = t; idx < C_ * C_; idx += 256)
        Ws[idx / C_][idx % C_] = W2[idx];
    int r = t >> 6, c = t & 63;
    int grow = blockIdx.x * 4 + r;
    int b = grow >> 9;
    float mu = g_mean1[b], rs = g_rstd1[b];
    Xs[r][c] = (g_Va[(size_t)grow * C_ + c] - mu) * rs;
    __syncthreads();
    float acc = b2[c];
#pragma unroll
    for (int j = 0; j < C_; j++)
        acc += Xs[r][j] * Ws[c][j];
    float v = V[(size_t)grow * C_ + c] + acc;
    g_Vp[(size_t)grow * C_ + c] = v;

    sh0[t] = (double)v;
    sh1[t] = (double)v * (double)v;
    __syncthreads();
    for (int o = 128; o > 0; o >>= 1) {
        if (t < o) { sh0[t] += sh0[t + o]; sh1[t] += sh1[t + o]; }
        __syncthreads();
    }
    if (t == 0)
        g_part2[blockIdx.x] = make_double2(sh0[0], sh1[0]);
}

// ---------------------------------------------------------------
// Kernel 6: out = (Vp - mean2[b]) * rstd2[b]
// ---------------------------------------------------------------
__global__ void k_final(float* __restrict__ out) {
    int idx = blockIdx.x * blockDim.x + threadIdx.x;
    int b = idx >> 15;
    out[idx] = (g_Vp[idx] - g_mean2[b]) * g_rstd2[b];
}

// ---------------------------------------------------------------
extern "C" void kernel_launch(void* const* d_in, const int* in_sizes, int n_in,
                              void* d_out, int out_size) {
    const float* V  = (const float*)d_in[0];
    const float* Q  = (const float*)d_in[1];
    const float* z  = (const float*)d_in[2];
    const float* zm = (const float*)d_in[3];
    const float* W1 = (const float*)d_in[4];
    const float* b1 = (const float*)d_in[5];
    const float* W2 = (const float*)d_in[6];
    const float* b2 = (const float*)d_in[7];
    float* out = (float*)d_out;

    k_linear1<<<(B_ * K_) / 4, 256>>>(Q, W1, b1);
    k_pass1<<<dim3(K_, B_), 256>>>(z, zm);
    k_pass2<<<dim3(I_, B_), 256>>>(z, zm);
    k_reduce<<<B_, 256>>>(0);
    k_linear2<<<(B_ * I_) / 4, 256>>>(V, W2, b2);
    k_reduce<<<B_, 256>>>(1);
    k_final<<<(B_ * I_ * C_) / 256, 256>>>(out);
}